// round 14
// baseline (speedup 1.0000x reference)
#include <cuda_runtime.h>
#include <cuda_fp16.h>
#include <cstdint>

// ============================================================================
// Problem constants
// ============================================================================
#define T_TOK   8192          // B*S tokens
#define HDIM    2048
#define NEXP    8
#define MAX_TILES 136         // sum ceil(count_e/128) <= 2T/128 + E
#define KCAT    4096          // merged K: [xh | u] / [wh | 32v]
#define KSTEPS  128           // KCAT / 32 per k-step
#define NSLOTF  (NEXP * T_TOK)   // fixed-capacity slot space (65536)

// ============================================================================
// PTX helpers — family-portable only (mma.sync / ldmatrix / cp.async)
// ============================================================================
__device__ __forceinline__ uint32_t smem_to_u32(const void* p) {
    uint32_t a;
    asm("{ .reg .u64 t; cvta.to.shared.u64 t, %1; cvt.u32.u64 %0, t; }"
        : "=r"(a) : "l"(p));
    return a;
}

#define CP_ASYNC16(smem, gmem) \
    asm volatile("cp.async.cg.shared.global [%0], [%1], 16;" \
        :: "r"(smem), "l"(gmem))
#define CP_COMMIT() asm volatile("cp.async.commit_group;" ::: "memory")
#define CP_WAIT2()  asm volatile("cp.async.wait_group 2;" ::: "memory")

__device__ __forceinline__ void ldsm_x4(uint32_t* r, uint32_t addr) {
    asm volatile("ldmatrix.sync.aligned.m8n8.x4.shared.b16 {%0,%1,%2,%3}, [%4];"
        : "=r"(r[0]), "=r"(r[1]), "=r"(r[2]), "=r"(r[3]) : "r"(addr));
}

// m16n8k16 fp16 HMMA, fp32 accumulate
__device__ __forceinline__ void mma16816(float* d, const uint32_t* a,
                                         const uint32_t* b) {
    asm volatile(
        "mma.sync.aligned.m16n8k16.row.col.f32.f16.f16.f32 "
        "{%0,%1,%2,%3}, {%4,%5,%6,%7}, {%8,%9}, {%0,%1,%2,%3};"
        : "+f"(d[0]), "+f"(d[1]), "+f"(d[2]), "+f"(d[3])
        : "r"(a[0]), "r"(a[1]), "r"(a[2]), "r"(a[3]), "r"(b[0]), "r"(b[1]));
}

// SW64 swizzle: XOR byte-offset bits[5:4] with bits[8:7] (row bits for 64B rows)
#define SW64(off) ((off) ^ (((off) >> 3) & 0x30))

// ============================================================================
// Device scratch — fixed-capacity slot layout: slot = e*T_TOK + pos.
// g_cursor must be 0 on entry of every launch: zero-init covers call 1;
// the combine kernel clears it at the end of each launch (graph-replay safe,
// deterministic — routing depends only on inputs).
// ============================================================================
__device__ int    g_cursor[NEXP];
__device__ int    g_slot_token[NSLOTF];    // zero-init; stale values stay in
__device__ float  g_slot_w[NSLOTF];        //   [0,T) so always a valid index
__device__ int    g_tok_slot[T_TOK * 2];

__device__ __half g_xc[(size_t)T_TOK * KCAT];              // 67 MB [xh | u], per TOKEN
__device__ __half g_wc[(size_t)NEXP * HDIM * KCAT];        // 134 MB [wh | 32v]
__device__ float  g_ybuf[(size_t)NSLOTF * HDIM];           // 536 MB, sparse-written

// ============================================================================
// K1: fused prep — register-resident router + x split-convert + w split-convert.
// Router: 128 blocks x (8 warps = 8 experts, 64 tokens). Each warp holds its
// expert's gw row in 16 float4 registers (loaded ONCE -> gw L2 traffic drops
// 512 MB -> 8 MB); the 8 warps share each token's x row via L1. Per-lane
// summation order + shuffle reduce identical to the per-token-warp version,
// so logits are bit-identical.
//
// Ootomo split:
//   A row (4096): [ xh = fp16(x) | u = fp16(xh/32 + (x-xh)) ]
//   B row (4096): [ wh = fp16(64w) | 32*fp16(wh/32 + (64w-wh)) ]  (32x exact)
// ============================================================================
#define TPB  64                                   // router tokens per block
#define RBLK (T_TOK / TPB)                        // 128 router blocks
#define XBLK (T_TOK * 512 / 256)                  // 16384
#define WBLK (NEXP * HDIM * HDIM / 4 / 256)       // 32768

__device__ __forceinline__ void split2(float a, float b, uint32_t& h,
                                       uint32_t& u, float post) {
    __half2 hh = __floats2half2_rn(a, b);
    float2 hf = __half22float2(hh);
    __half2 uu = __floats2half2_rn((hf.x * 0.03125f + (a - hf.x)) * post,
                                   (hf.y * 0.03125f + (b - hf.y)) * post);
    h = *(uint32_t*)&hh;
    u = *(uint32_t*)&uu;
}

__global__ void moe_prep_kernel(const float* __restrict__ x,
                                const float* __restrict__ gw,
                                const float* __restrict__ ew,
                                float* __restrict__ logits_out) {
    __shared__ float s_log[TPB * NEXP];
    if (blockIdx.x < RBLK) {
        // ---- router: warp = expert (gw row in registers), 64 tokens/block ----
        int w = threadIdx.x >> 5, lane = threadIdx.x & 31;
        int tok0 = blockIdx.x * TPB;
        const float4* gr = (const float4*)(gw + (size_t)w * HDIM);
        float4 g[16];
#pragma unroll
        for (int i = 0; i < 16; i++) g[i] = gr[i * 32 + lane];
        for (int t = 0; t < TPB; t++) {
            const float4* xr = (const float4*)(x + (size_t)(tok0 + t) * HDIM);
            float a = 0.f;
#pragma unroll
            for (int i = 0; i < 16; i++) {
                float4 xv = xr[i * 32 + lane];
                a += xv.x * g[i].x + xv.y * g[i].y
                   + xv.z * g[i].z + xv.w * g[i].w;
            }
#pragma unroll
            for (int off = 16; off; off >>= 1)
                a += __shfl_xor_sync(0xFFFFFFFFu, a, off);
            if (lane == 0) s_log[t * NEXP + w] = a;
        }
        __syncthreads();
        if (threadIdx.x < TPB) {
            int tok = tok0 + threadIdx.x;
            float l[NEXP];
#pragma unroll
            for (int e = 0; e < NEXP; e++) l[e] = s_log[threadIdx.x * NEXP + e];
            ((float4*)logits_out)[tok * 2]     = make_float4(l[0], l[1], l[2], l[3]);
            ((float4*)logits_out)[tok * 2 + 1] = make_float4(l[4], l[5], l[6], l[7]);
            int i1 = 0; float l1 = l[0];
#pragma unroll
            for (int e = 1; e < NEXP; e++) if (l[e] > l1) { l1 = l[e]; i1 = e; }
            int i2 = -1; float l2 = -3.4e38f;
#pragma unroll
            for (int e = 0; e < NEXP; e++)
                if (e != i1 && l[e] > l2) { l2 = l[e]; i2 = e; }
            float ex = expf(l2 - l1);
            float w1 = 1.0f / (1.0f + ex);
            float w2 = ex / (1.0f + ex);
            int p1 = atomicAdd(&g_cursor[i1], 1);
            int s1 = i1 * T_TOK + p1;
            g_slot_token[s1] = tok;  g_slot_w[s1] = w1;
            g_tok_slot[tok * 2] = s1;
            int p2 = atomicAdd(&g_cursor[i2], 1);
            int s2 = i2 * T_TOK + p2;
            g_slot_token[s2] = tok;  g_slot_w[s2] = w2;
            g_tok_slot[tok * 2 + 1] = s2;
        }
    } else if (blockIdx.x < RBLK + XBLK) {
        // ---- x split-convert (per TOKEN layout) ----
        int i = (blockIdx.x - RBLK) * 256 + threadIdx.x;
        int tok = i >> 9;
        int j = i & 511;
        float4 vv = ((const float4*)x)[(size_t)tok * 512 + j];
        uint32_t h0, u0, h1, u1;
        split2(vv.x, vv.y, h0, u0, 1.0f);
        split2(vv.z, vv.w, h1, u1, 1.0f);
        size_t rb = (size_t)tok * (KCAT / 4);           // uint2 units per row
        ((uint2*)g_xc)[rb + j]       = make_uint2(h0, h1);
        ((uint2*)g_xc)[rb + 512 + j] = make_uint2(u0, u1);
    } else {
        // ---- w split-convert ----
        size_t i = (size_t)(blockIdx.x - RBLK - XBLK) * 256 + threadIdx.x;
        int row = (int)(i >> 9);                        // e*HDIM + n
        int j = (int)(i & 511);
        float4 vv = ((const float4*)ew)[i];
        uint32_t h0, u0, h1, u1;
        // post=32 scales the correction term exactly (power of 2 in fp16)
        split2(vv.x * 64.f, vv.y * 64.f, h0, u0, 32.0f);
        split2(vv.z * 64.f, vv.w * 64.f, h1, u1, 32.0f);
        size_t rb = (size_t)row * (KCAT / 4);
        ((uint2*)g_wc)[rb + j]       = make_uint2(h0, h1);
        ((uint2*)g_wc)[rb + 512 + j] = make_uint2(u0, u1);
    }
}

// ============================================================================
// K2: grouped GEMM — 128x128xK4096 merged Ootomo, single fp32 acc set,
// 4 warps (2x2 grid, 64x64 warp tile), 2 CTAs/SM, 4-stage cp.async, SW64.
// Self-scheduling: each CTA derives (expert, mbase) from g_cursor with an
// 8-step prefix walk (no tile map, no scan kernel).
// Single __syncthreads per k-step; stage (kt+3)&3 was consumed in kt-1.
// Mid-loop: acc *= 31/32 (fp32-exact) between the xh*wh and u*32v halves.
// Epilogue: weighted rows -> ybuf (padding rows never read by combine).
// ============================================================================
#define MAT_B     8192                        // 128 rows x 64B
#define STAGE_B   (2 * MAT_B)                 // 16384 (A, B)
#define NSTAGE    4
#define SMEM_DYN  (1024 + NSTAGE * STAGE_B)   // 66560 B -> 2 CTAs/SM

__global__ void __launch_bounds__(128, 2)
moe_gemm_kernel() {
    // per-CTA tile schedule from cursors (8 L2-hot ints)
    int tile = blockIdx.y;
    int e = -1, mbase = 0, nt = 0;
#pragma unroll
    for (int ee = 0; ee < NEXP; ee++) {
        int tiles = (g_cursor[ee] + 127) >> 7;
        if (e < 0 && tile < nt + tiles) {
            e = ee;
            mbase = ee * T_TOK + (tile - nt) * 128;
        }
        nt += tiles;
    }
    if (e < 0) return;
    int n0 = blockIdx.x * 128;

    extern __shared__ char dsm[];
    float* s_fr    = (float*)dsm;             // 128: slotw/64 per row
    int*   s_token = (int*)(dsm + 512);       // 128: token per row
    uint32_t st0 = smem_to_u32(dsm) + 1024;

    int tid = threadIdx.x, lane = tid & 31, wid = tid >> 5;
    int wm = wid >> 1, wn = wid & 1;          // 2x2 grid, warp 64(M)x64(N)

    if (tid < 128) {
        s_fr[tid]    = g_slot_w[mbase + tid] * (1.0f / 64.0f);
        s_token[tid] = g_slot_token[mbase + tid];
    }
    __syncthreads();

    const __half* Bg = g_wc + ((size_t)e * HDIM + n0) * KCAT;

    // precompute per-thread fill pointers (8 chunks: 4 A via token gather, 4 B)
    const __half* gsrc[8];
    uint32_t sdst[8];
#pragma unroll
    for (int i = 0; i < 8; i++) {
        int cid = tid + i * 128;
        int mat = cid >> 9;                   // 0=A, 1=B
        int win = cid & 511;
        int rr  = win >> 2;
        int cc  = win & 3;
        if (mat == 0) {
            int tok = s_token[rr];
            gsrc[i] = g_xc + (size_t)tok * KCAT + cc * 8;
        } else {
            gsrc[i] = Bg + (size_t)rr * KCAT + cc * 8;
        }
        sdst[i] = st0 + mat * MAT_B + SW64((uint32_t)(rr * 64 + cc * 16));
    }

    auto fill = [&](int stage, int kt) {
        uint32_t so = (uint32_t)(stage * STAGE_B);
        int k0 = kt * 32;
#pragma unroll
        for (int i = 0; i < 8; i++)
            CP_ASYNC16(sdst[i] + so, gsrc[i] + k0);
    };

    fill(0, 0); CP_COMMIT();
    fill(1, 1); CP_COMMIT();
    fill(2, 2); CP_COMMIT();

    float acc[4][8][4];
#pragma unroll
    for (int a = 0; a < 4; a++)
#pragma unroll
        for (int b = 0; b < 8; b++)
#pragma unroll
            for (int c = 0; c < 4; c++) acc[a][b][c] = 0.f;

    for (int kt = 0; kt < KSTEPS; kt++) {
        // between halves: acc = T1 -> scale by 31/32 (fp32-exact cancellation)
        if (kt == KSTEPS / 2) {
#pragma unroll
            for (int a = 0; a < 4; a++)
#pragma unroll
                for (int b = 0; b < 8; b++)
#pragma unroll
                    for (int c = 0; c < 4; c++) acc[a][b][c] *= 0.96875f;
        }
        CP_WAIT2();
        __syncthreads();                      // single sync per k-step

        int nxt = kt + 3;                     // stage (kt+3)&3 was read in kt-1
        if (nxt < KSTEPS) fill(nxt & 3, nxt);
        CP_COMMIT();

        uint32_t sbase = st0 + (kt & 3) * STAGE_B;
        uint32_t sA = sbase, sB = sbase + MAT_B;
#pragma unroll
        for (int k16 = 0; k16 < 2; k16++) {
            uint32_t af[4][4];
#pragma unroll
            for (int mi = 0; mi < 4; mi++) {
                uint32_t ad = SW64((uint32_t)(
                    (wm * 64 + mi * 16 + (lane & 15)) * 64
                    + k16 * 32 + (lane >> 4) * 16));
                ldsm_x4(af[mi], sA + ad);
            }
            uint32_t bf[4][4];
#pragma unroll
            for (int jj = 0; jj < 4; jj++) {
                uint32_t bd = SW64((uint32_t)(
                    (wn * 64 + jj * 16 + ((lane >> 4) << 3) + (lane & 7)) * 64
                    + k16 * 32 + (((lane >> 3) & 1) << 4)));
                ldsm_x4(bf[jj], sB + bd);
            }
            // 32 HMMAs per k16, acc reuse distance 32
#pragma unroll
            for (int mi = 0; mi < 4; mi++)
#pragma unroll
                for (int jj = 0; jj < 4; jj++)
#pragma unroll
                    for (int s = 0; s < 2; s++)
                        mma16816(acc[mi][jj * 2 + s], af[mi], &bf[jj][s * 2]);
        }
    }

    // epilogue: y = acc * slotw/64 -> ybuf
#pragma unroll
    for (int mi = 0; mi < 4; mi++) {
        int r0 = wm * 64 + mi * 16 + (lane >> 2);
        float f0 = s_fr[r0], f1 = s_fr[r0 + 8];
        size_t o0 = (size_t)(mbase + r0) * HDIM + n0;
#pragma unroll
        for (int n8 = 0; n8 < 8; n8++) {
            int c = wn * 64 + n8 * 8 + (lane & 3) * 2;
            *(float2*)(g_ybuf + o0 + c) =
                make_float2(acc[mi][n8][0] * f0, acc[mi][n8][1] * f0);
            *(float2*)(g_ybuf + o0 + (size_t)8 * HDIM + c) =
                make_float2(acc[mi][n8][2] * f1, acc[mi][n8][3] * f1);
        }
    }
}

// ============================================================================
// K3: combine — out[t] = ybuf[slot0(t)] + ybuf[slot1(t)]; block 0 also
// resets the cursors for the next launch (graph replay invariant; runs
// after the GEMM's g_cursor reads).
// ============================================================================
__global__ void moe_combine_kernel(float* __restrict__ out) {
    if (blockIdx.x == 0 && threadIdx.x < NEXP) g_cursor[threadIdx.x] = 0;
    int i = blockIdx.x * blockDim.x + threadIdx.x;
    int t  = i >> 9;
    int h4 = i & 511;
    int s0 = g_tok_slot[2 * t + 0];
    int s1 = g_tok_slot[2 * t + 1];
    float4 a = *(const float4*)(g_ybuf + (size_t)s0 * HDIM + h4 * 4);
    float4 b = *(const float4*)(g_ybuf + (size_t)s1 * HDIM + h4 * 4);
    float4 o;
    o.x = a.x + b.x; o.y = a.y + b.y; o.z = a.z + b.z; o.w = a.w + b.w;
    ((float4*)out)[i] = o;
}

// ============================================================================
// Launch — 3 kernels total
// ============================================================================
extern "C" void kernel_launch(void* const* d_in, const int* in_sizes, int n_in,
                              void* d_out, int out_size) {
    const float* x  = (const float*)d_in[0];   // hidden_states [T, H]
    const float* gw = (const float*)d_in[1];   // gate_w [E, H]
    const float* ew = (const float*)d_in[2];   // expert_w [E, H, H]
    float* out    = (float*)d_out;             // [T, H]
    float* logits = out + (size_t)T_TOK * HDIM;

    cudaFuncSetAttribute(moe_gemm_kernel,
                         cudaFuncAttributeMaxDynamicSharedMemorySize, SMEM_DYN);

    moe_prep_kernel<<<RBLK + XBLK + WBLK, 256>>>(x, gw, ew, logits);
    moe_gemm_kernel<<<dim3(16, MAX_TILES), 128, SMEM_DYN>>>();
    moe_combine_kernel<<<(T_TOK * (HDIM / 4)) / 256, 256>>>(out);
}

// round 15
// speedup vs baseline: 1.4163x; 1.4163x over previous
#include <cuda_runtime.h>
#include <cuda_fp16.h>
#include <cstdint>

// ============================================================================
// Problem constants
// ============================================================================
#define T_TOK   8192          // B*S tokens
#define HDIM    2048
#define NEXP    8
#define MAX_TILES 136         // sum ceil(count_e/128) <= 2T/128 + E
#define KCAT    4096          // merged K: [xh | u] / [wh | 32v]
#define KSTEPS  128           // KCAT / 32 per k-step
#define NSLOTF  (NEXP * T_TOK)   // fixed-capacity slot space (65536)

// ============================================================================
// PTX helpers — family-portable only (mma.sync / ldmatrix / cp.async)
// ============================================================================
__device__ __forceinline__ uint32_t smem_to_u32(const void* p) {
    uint32_t a;
    asm("{ .reg .u64 t; cvta.to.shared.u64 t, %1; cvt.u32.u64 %0, t; }"
        : "=r"(a) : "l"(p));
    return a;
}

#define CP_ASYNC16(smem, gmem) \
    asm volatile("cp.async.cg.shared.global [%0], [%1], 16;" \
        :: "r"(smem), "l"(gmem))
#define CP_COMMIT() asm volatile("cp.async.commit_group;" ::: "memory")
#define CP_WAIT2()  asm volatile("cp.async.wait_group 2;" ::: "memory")

__device__ __forceinline__ void ldsm_x4(uint32_t* r, uint32_t addr) {
    asm volatile("ldmatrix.sync.aligned.m8n8.x4.shared.b16 {%0,%1,%2,%3}, [%4];"
        : "=r"(r[0]), "=r"(r[1]), "=r"(r[2]), "=r"(r[3]) : "r"(addr));
}

// m16n8k16 fp16 HMMA, fp32 accumulate
__device__ __forceinline__ void mma16816(float* d, const uint32_t* a,
                                         const uint32_t* b) {
    asm volatile(
        "mma.sync.aligned.m16n8k16.row.col.f32.f16.f16.f32 "
        "{%0,%1,%2,%3}, {%4,%5,%6,%7}, {%8,%9}, {%0,%1,%2,%3};"
        : "+f"(d[0]), "+f"(d[1]), "+f"(d[2]), "+f"(d[3])
        : "r"(a[0]), "r"(a[1]), "r"(a[2]), "r"(a[3]), "r"(b[0]), "r"(b[1]));
}

// SW64 swizzle: XOR byte-offset bits[5:4] with bits[8:7] (row bits for 64B rows)
#define SW64(off) ((off) ^ (((off) >> 3) & 0x30))

// ============================================================================
// Device scratch — fixed-capacity slot layout: slot = e*T_TOK + pos.
// g_cursor must be 0 on entry of every launch: zero-init covers call 1;
// the combine kernel clears it at the end of each launch (graph-replay safe,
// deterministic — routing depends only on inputs).
// ============================================================================
__device__ int    g_cursor[NEXP];
__device__ int    g_slot_token[NSLOTF];    // zero-init; stale values stay in
__device__ float  g_slot_w[NSLOTF];        //   [0,T) so always a valid index
__device__ int    g_tok_slot[T_TOK * 2];

__device__ __half g_xc[(size_t)T_TOK * KCAT];              // 67 MB [xh | u], per TOKEN
__device__ __half g_wc[(size_t)NEXP * HDIM * KCAT];        // 134 MB [wh | 32v]
__device__ float  g_ybuf[(size_t)NSLOTF * HDIM];           // 536 MB, sparse-written

// ============================================================================
// K1: router — SEPARATE kernel (register-heavy branch must not tax the
// convert kernel's occupancy — R14 lesson). 128 blocks x (8 warps = 8
// experts, 64 tokens). Each warp holds its expert's gw row in 16 float4
// registers (gw read ONCE; no 512 MB L2 re-stream). Per-lane summation
// order + shuffle reduce keep logits bit-identical.
// ============================================================================
#define TPB  64                                   // router tokens per block
#define RBLK (T_TOK / TPB)                        // 128 router blocks

__global__ void moe_router_kernel(const float* __restrict__ x,
                                  const float* __restrict__ gw,
                                  float* __restrict__ logits_out) {
    __shared__ float s_log[TPB * NEXP];
    int w = threadIdx.x >> 5, lane = threadIdx.x & 31;
    int tok0 = blockIdx.x * TPB;
    const float4* gr = (const float4*)(gw + (size_t)w * HDIM);
    float4 g[16];
#pragma unroll
    for (int i = 0; i < 16; i++) g[i] = gr[i * 32 + lane];
    for (int t = 0; t < TPB; t++) {
        const float4* xr = (const float4*)(x + (size_t)(tok0 + t) * HDIM);
        float a = 0.f;
#pragma unroll
        for (int i = 0; i < 16; i++) {
            float4 xv = xr[i * 32 + lane];
            a += xv.x * g[i].x + xv.y * g[i].y
               + xv.z * g[i].z + xv.w * g[i].w;
        }
#pragma unroll
        for (int off = 16; off; off >>= 1)
            a += __shfl_xor_sync(0xFFFFFFFFu, a, off);
        if (lane == 0) s_log[t * NEXP + w] = a;
    }
    __syncthreads();
    if (threadIdx.x < TPB) {
        int tok = tok0 + threadIdx.x;
        float l[NEXP];
#pragma unroll
        for (int e = 0; e < NEXP; e++) l[e] = s_log[threadIdx.x * NEXP + e];
        ((float4*)logits_out)[tok * 2]     = make_float4(l[0], l[1], l[2], l[3]);
        ((float4*)logits_out)[tok * 2 + 1] = make_float4(l[4], l[5], l[6], l[7]);
        int i1 = 0; float l1 = l[0];
#pragma unroll
        for (int e = 1; e < NEXP; e++) if (l[e] > l1) { l1 = l[e]; i1 = e; }
        int i2 = -1; float l2 = -3.4e38f;
#pragma unroll
        for (int e = 0; e < NEXP; e++)
            if (e != i1 && l[e] > l2) { l2 = l[e]; i2 = e; }
        float ex = expf(l2 - l1);
        float w1 = 1.0f / (1.0f + ex);
        float w2 = ex / (1.0f + ex);
        int p1 = atomicAdd(&g_cursor[i1], 1);
        int s1 = i1 * T_TOK + p1;
        g_slot_token[s1] = tok;  g_slot_w[s1] = w1;
        g_tok_slot[tok * 2] = s1;
        int p2 = atomicAdd(&g_cursor[i2], 1);
        int s2 = i2 * T_TOK + p2;
        g_slot_token[s2] = tok;  g_slot_w[s2] = w2;
        g_tok_slot[tok * 2 + 1] = s2;
    }
}

// ============================================================================
// K2: split-convert (Ootomo, merged-K layout) — lean kernel (low regs, full
// occupancy, pure DRAM streaming).
//   A row (4096): [ xh = fp16(x) | u = fp16(xh/32 + (x-xh)) ]
//   B row (4096): [ wh = fp16(64w) | 32*fp16(wh/32 + (64w-wh)) ]  (32x exact)
// ============================================================================
#define XBLK (T_TOK * 512 / 256)                  // 16384
#define WBLK (NEXP * HDIM * HDIM / 4 / 256)       // 32768

__device__ __forceinline__ void split2(float a, float b, uint32_t& h,
                                       uint32_t& u, float post) {
    __half2 hh = __floats2half2_rn(a, b);
    float2 hf = __half22float2(hh);
    __half2 uu = __floats2half2_rn((hf.x * 0.03125f + (a - hf.x)) * post,
                                   (hf.y * 0.03125f + (b - hf.y)) * post);
    h = *(uint32_t*)&hh;
    u = *(uint32_t*)&uu;
}

__global__ void moe_convert_kernel(const float* __restrict__ x,
                                   const float* __restrict__ ew) {
    if (blockIdx.x < XBLK) {
        // ---- x split-convert (per TOKEN layout) ----
        int i = blockIdx.x * 256 + threadIdx.x;
        int tok = i >> 9;
        int j = i & 511;
        float4 vv = ((const float4*)x)[(size_t)tok * 512 + j];
        uint32_t h0, u0, h1, u1;
        split2(vv.x, vv.y, h0, u0, 1.0f);
        split2(vv.z, vv.w, h1, u1, 1.0f);
        size_t rb = (size_t)tok * (KCAT / 4);           // uint2 units per row
        ((uint2*)g_xc)[rb + j]       = make_uint2(h0, h1);
        ((uint2*)g_xc)[rb + 512 + j] = make_uint2(u0, u1);
    } else {
        // ---- w split-convert ----
        size_t i = (size_t)(blockIdx.x - XBLK) * 256 + threadIdx.x;
        int row = (int)(i >> 9);                        // e*HDIM + n
        int j = (int)(i & 511);
        float4 vv = ((const float4*)ew)[i];
        uint32_t h0, u0, h1, u1;
        // post=32 scales the correction term exactly (power of 2 in fp16)
        split2(vv.x * 64.f, vv.y * 64.f, h0, u0, 32.0f);
        split2(vv.z * 64.f, vv.w * 64.f, h1, u1, 32.0f);
        size_t rb = (size_t)row * (KCAT / 4);
        ((uint2*)g_wc)[rb + j]       = make_uint2(h0, h1);
        ((uint2*)g_wc)[rb + 512 + j] = make_uint2(u0, u1);
    }
}

// ============================================================================
// K3: grouped GEMM — 128x128xK4096 merged Ootomo, single fp32 acc set,
// 4 warps (2x2 grid, 64x64 warp tile), 2 CTAs/SM, 4-stage cp.async, SW64.
// Self-scheduling: each CTA derives (expert, mbase) from g_cursor with an
// 8-step prefix walk (no tile map, no scan kernel).
// Single __syncthreads per k-step; stage (kt+3)&3 was consumed in kt-1.
// Mid-loop: acc *= 31/32 (fp32-exact) between the xh*wh and u*32v halves.
// Epilogue: weighted rows -> ybuf (padding rows never read by combine).
// ============================================================================
#define MAT_B     8192                        // 128 rows x 64B
#define STAGE_B   (2 * MAT_B)                 // 16384 (A, B)
#define NSTAGE    4
#define SMEM_DYN  (1024 + NSTAGE * STAGE_B)   // 66560 B -> 2 CTAs/SM

__global__ void __launch_bounds__(128, 2)
moe_gemm_kernel() {
    // per-CTA tile schedule from cursors (8 L2-hot ints)
    int tile = blockIdx.y;
    int e = -1, mbase = 0, nt = 0;
#pragma unroll
    for (int ee = 0; ee < NEXP; ee++) {
        int tiles = (g_cursor[ee] + 127) >> 7;
        if (e < 0 && tile < nt + tiles) {
            e = ee;
            mbase = ee * T_TOK + (tile - nt) * 128;
        }
        nt += tiles;
    }
    if (e < 0) return;
    int n0 = blockIdx.x * 128;

    extern __shared__ char dsm[];
    float* s_fr    = (float*)dsm;             // 128: slotw/64 per row
    int*   s_token = (int*)(dsm + 512);       // 128: token per row
    uint32_t st0 = smem_to_u32(dsm) + 1024;

    int tid = threadIdx.x, lane = tid & 31, wid = tid >> 5;
    int wm = wid >> 1, wn = wid & 1;          // 2x2 grid, warp 64(M)x64(N)

    if (tid < 128) {
        s_fr[tid]    = g_slot_w[mbase + tid] * (1.0f / 64.0f);
        s_token[tid] = g_slot_token[mbase + tid];
    }
    __syncthreads();

    const __half* Bg = g_wc + ((size_t)e * HDIM + n0) * KCAT;

    // precompute per-thread fill pointers (8 chunks: 4 A via token gather, 4 B)
    const __half* gsrc[8];
    uint32_t sdst[8];
#pragma unroll
    for (int i = 0; i < 8; i++) {
        int cid = tid + i * 128;
        int mat = cid >> 9;                   // 0=A, 1=B
        int win = cid & 511;
        int rr  = win >> 2;
        int cc  = win & 3;
        if (mat == 0) {
            int tok = s_token[rr];
            gsrc[i] = g_xc + (size_t)tok * KCAT + cc * 8;
        } else {
            gsrc[i] = Bg + (size_t)rr * KCAT + cc * 8;
        }
        sdst[i] = st0 + mat * MAT_B + SW64((uint32_t)(rr * 64 + cc * 16));
    }

    auto fill = [&](int stage, int kt) {
        uint32_t so = (uint32_t)(stage * STAGE_B);
        int k0 = kt * 32;
#pragma unroll
        for (int i = 0; i < 8; i++)
            CP_ASYNC16(sdst[i] + so, gsrc[i] + k0);
    };

    fill(0, 0); CP_COMMIT();
    fill(1, 1); CP_COMMIT();
    fill(2, 2); CP_COMMIT();

    float acc[4][8][4];
#pragma unroll
    for (int a = 0; a < 4; a++)
#pragma unroll
        for (int b = 0; b < 8; b++)
#pragma unroll
            for (int c = 0; c < 4; c++) acc[a][b][c] = 0.f;

    for (int kt = 0; kt < KSTEPS; kt++) {
        // between halves: acc = T1 -> scale by 31/32 (fp32-exact cancellation)
        if (kt == KSTEPS / 2) {
#pragma unroll
            for (int a = 0; a < 4; a++)
#pragma unroll
                for (int b = 0; b < 8; b++)
#pragma unroll
                    for (int c = 0; c < 4; c++) acc[a][b][c] *= 0.96875f;
        }
        CP_WAIT2();
        __syncthreads();                      // single sync per k-step

        int nxt = kt + 3;                     // stage (kt+3)&3 was read in kt-1
        if (nxt < KSTEPS) fill(nxt & 3, nxt);
        CP_COMMIT();

        uint32_t sbase = st0 + (kt & 3) * STAGE_B;
        uint32_t sA = sbase, sB = sbase + MAT_B;
#pragma unroll
        for (int k16 = 0; k16 < 2; k16++) {
            uint32_t af[4][4];
#pragma unroll
            for (int mi = 0; mi < 4; mi++) {
                uint32_t ad = SW64((uint32_t)(
                    (wm * 64 + mi * 16 + (lane & 15)) * 64
                    + k16 * 32 + (lane >> 4) * 16));
                ldsm_x4(af[mi], sA + ad);
            }
            uint32_t bf[4][4];
#pragma unroll
            for (int jj = 0; jj < 4; jj++) {
                uint32_t bd = SW64((uint32_t)(
                    (wn * 64 + jj * 16 + ((lane >> 4) << 3) + (lane & 7)) * 64
                    + k16 * 32 + (((lane >> 3) & 1) << 4)));
                ldsm_x4(bf[jj], sB + bd);
            }
            // 32 HMMAs per k16, acc reuse distance 32
#pragma unroll
            for (int mi = 0; mi < 4; mi++)
#pragma unroll
                for (int jj = 0; jj < 4; jj++)
#pragma unroll
                    for (int s = 0; s < 2; s++)
                        mma16816(acc[mi][jj * 2 + s], af[mi], &bf[jj][s * 2]);
        }
    }

    // epilogue: y = acc * slotw/64 -> ybuf
#pragma unroll
    for (int mi = 0; mi < 4; mi++) {
        int r0 = wm * 64 + mi * 16 + (lane >> 2);
        float f0 = s_fr[r0], f1 = s_fr[r0 + 8];
        size_t o0 = (size_t)(mbase + r0) * HDIM + n0;
#pragma unroll
        for (int n8 = 0; n8 < 8; n8++) {
            int c = wn * 64 + n8 * 8 + (lane & 3) * 2;
            *(float2*)(g_ybuf + o0 + c) =
                make_float2(acc[mi][n8][0] * f0, acc[mi][n8][1] * f0);
            *(float2*)(g_ybuf + o0 + (size_t)8 * HDIM + c) =
                make_float2(acc[mi][n8][2] * f1, acc[mi][n8][3] * f1);
        }
    }
}

// ============================================================================
// K4: combine — out[t] = ybuf[slot0(t)] + ybuf[slot1(t)]; block 0 also
// resets the cursors for the next launch (graph replay invariant; runs
// after the GEMM's g_cursor reads).
// ============================================================================
__global__ void moe_combine_kernel(float* __restrict__ out) {
    if (blockIdx.x == 0 && threadIdx.x < NEXP) g_cursor[threadIdx.x] = 0;
    int i = blockIdx.x * blockDim.x + threadIdx.x;
    int t  = i >> 9;
    int h4 = i & 511;
    int s0 = g_tok_slot[2 * t + 0];
    int s1 = g_tok_slot[2 * t + 1];
    float4 a = *(const float4*)(g_ybuf + (size_t)s0 * HDIM + h4 * 4);
    float4 b = *(const float4*)(g_ybuf + (size_t)s1 * HDIM + h4 * 4);
    float4 o;
    o.x = a.x + b.x; o.y = a.y + b.y; o.z = a.z + b.z; o.w = a.w + b.w;
    ((float4*)out)[i] = o;
}

// ============================================================================
// Launch — 4 kernels (router split back out; R14 occupancy lesson)
// ============================================================================
extern "C" void kernel_launch(void* const* d_in, const int* in_sizes, int n_in,
                              void* d_out, int out_size) {
    const float* x  = (const float*)d_in[0];   // hidden_states [T, H]
    const float* gw = (const float*)d_in[1];   // gate_w [E, H]
    const float* ew = (const float*)d_in[2];   // expert_w [E, H, H]
    float* out    = (float*)d_out;             // [T, H]
    float* logits = out + (size_t)T_TOK * HDIM;

    cudaFuncSetAttribute(moe_gemm_kernel,
                         cudaFuncAttributeMaxDynamicSharedMemorySize, SMEM_DYN);

    moe_router_kernel<<<RBLK, 256>>>(x, gw, logits);
    moe_convert_kernel<<<XBLK + WBLK, 256>>>(x, ew);
    moe_gemm_kernel<<<dim3(16, MAX_TILES), 128, SMEM_DYN>>>();
    moe_combine_kernel<<<(T_TOK * (HDIM / 4)) / 256, 256>>>(out);
}

// round 16
// speedup vs baseline: 1.6696x; 1.1788x over previous
#include <cuda_runtime.h>
#include <cuda_fp16.h>
#include <cstdint>

// ============================================================================
// Problem constants
// ============================================================================
#define T_TOK   8192          // B*S tokens
#define HDIM    2048
#define NEXP    8
#define MAX_TILES 136         // sum ceil(count_e/128) <= 2T/128 + E
#define KCAT    4096          // merged K: [xh | u] / [wh | 32v]
#define KSTEPS  128           // KCAT / 32 per k-step
#define NSLOTF  (NEXP * T_TOK)   // fixed-capacity slot space (65536)

// ============================================================================
// PTX helpers — family-portable only (mma.sync / ldmatrix / cp.async)
// ============================================================================
__device__ __forceinline__ uint32_t smem_to_u32(const void* p) {
    uint32_t a;
    asm("{ .reg .u64 t; cvta.to.shared.u64 t, %1; cvt.u32.u64 %0, t; }"
        : "=r"(a) : "l"(p));
    return a;
}

#define CP_ASYNC16(smem, gmem) \
    asm volatile("cp.async.cg.shared.global [%0], [%1], 16;" \
        :: "r"(smem), "l"(gmem))
#define CP_COMMIT() asm volatile("cp.async.commit_group;" ::: "memory")
#define CP_WAIT2()  asm volatile("cp.async.wait_group 2;" ::: "memory")

__device__ __forceinline__ void ldsm_x4(uint32_t* r, uint32_t addr) {
    asm volatile("ldmatrix.sync.aligned.m8n8.x4.shared.b16 {%0,%1,%2,%3}, [%4];"
        : "=r"(r[0]), "=r"(r[1]), "=r"(r[2]), "=r"(r[3]) : "r"(addr));
}

// m16n8k16 fp16 HMMA, fp32 accumulate
__device__ __forceinline__ void mma16816(float* d, const uint32_t* a,
                                         const uint32_t* b) {
    asm volatile(
        "mma.sync.aligned.m16n8k16.row.col.f32.f16.f16.f32 "
        "{%0,%1,%2,%3}, {%4,%5,%6,%7}, {%8,%9}, {%0,%1,%2,%3};"
        : "+f"(d[0]), "+f"(d[1]), "+f"(d[2]), "+f"(d[3])
        : "r"(a[0]), "r"(a[1]), "r"(a[2]), "r"(a[3]), "r"(b[0]), "r"(b[1]));
}

// SW64 swizzle: XOR byte-offset bits[5:4] with bits[8:7] (row bits for 64B rows)
#define SW64(off) ((off) ^ (((off) >> 3) & 0x30))

// ============================================================================
// Device scratch — fixed-capacity slot layout: slot = e*T_TOK + pos.
// g_cursor must be 0 on entry of every launch: zero-init covers call 1;
// the combine kernel clears it at the end of each launch (graph-replay safe,
// deterministic — routing depends only on inputs).
// ============================================================================
__device__ int    g_cursor[NEXP];
__device__ int    g_slot_token[NSLOTF];    // zero-init; stale values stay in
__device__ float  g_slot_w[NSLOTF];        //   [0,T) so always a valid index
__device__ int    g_tok_slot[T_TOK * 2];

__device__ __half g_xc[(size_t)T_TOK * KCAT];              // 67 MB [xh | u], per TOKEN
__device__ __half g_wc[(size_t)NEXP * HDIM * KCAT];        // 134 MB [wh | 32v]
__device__ float  g_ybuf[(size_t)NSLOTF * HDIM];           // 536 MB, sparse-written

// ============================================================================
// K1: fused prep — batch-2 router + 32B/thread split-converts.
// Router range: 512 blocks x 8 warps x 2 tokens (warp-parallel; gw fetched
// once per pair -> 256 MB L2, half of R13). Per-token accumulation order and
// shuffle reduce identical to prior rounds -> logits bit-identical.
// Convert ranges: each thread loads 2 consecutive float4 (32 B in flight,
// MLP 2) and writes merged 16 B uint4 stores — keeps DRAM saturated at
// reduced occupancy (R14/R15 lesson).
//
// Ootomo split:
//   A row (4096): [ xh = fp16(x) | u = fp16(xh/32 + (x-xh)) ]
//   B row (4096): [ wh = fp16(64w) | 32*fp16(wh/32 + (64w-wh)) ]  (32x exact)
// ============================================================================
#define RBLK  (T_TOK / 16)                        // 512 router blocks
#define X2BLK (T_TOK)                             // 8192: one block per token
#define W2BLK (NEXP * HDIM * HDIM / 8 / 256)      // 16384 w-convert blocks

__device__ __forceinline__ void split2(float a, float b, uint32_t& h,
                                       uint32_t& u, float post) {
    __half2 hh = __floats2half2_rn(a, b);
    float2 hf = __half22float2(hh);
    __half2 uu = __floats2half2_rn((hf.x * 0.03125f + (a - hf.x)) * post,
                                   (hf.y * 0.03125f + (b - hf.y)) * post);
    h = *(uint32_t*)&hh;
    u = *(uint32_t*)&uu;
}

__global__ void moe_prep_kernel(const float* __restrict__ x,
                                const float* __restrict__ gw,
                                const float* __restrict__ ew,
                                float* __restrict__ logits_out) {
    if (blockIdx.x < RBLK) {
        // ---- router: warp handles 2 tokens; gw loads amortized x2 ----
        int w = threadIdx.x >> 5, lane = threadIdx.x & 31;
        int tok = blockIdx.x * 16 + w * 2;          // tokens tok, tok+1
        const float4* x0 = (const float4*)(x + (size_t)tok * HDIM);
        const float4* x1 = (const float4*)(x + (size_t)(tok + 1) * HDIM);
        float a0[NEXP], a1[NEXP];
#pragma unroll
        for (int e = 0; e < NEXP; e++) { a0[e] = 0.f; a1[e] = 0.f; }
        for (int i = 0; i < 16; i++) {
            float4 v0 = x0[i * 32 + lane];
            float4 v1 = x1[i * 32 + lane];
#pragma unroll
            for (int e = 0; e < NEXP; e++) {
                float4 gv = ((const float4*)(gw + e * HDIM))[i * 32 + lane];
                a0[e] += v0.x * gv.x + v0.y * gv.y + v0.z * gv.z + v0.w * gv.w;
                a1[e] += v1.x * gv.x + v1.y * gv.y + v1.z * gv.z + v1.w * gv.w;
            }
        }
#pragma unroll
        for (int e = 0; e < NEXP; e++) {
#pragma unroll
            for (int off = 16; off; off >>= 1)
                a0[e] += __shfl_xor_sync(0xFFFFFFFFu, a0[e], off);
#pragma unroll
            for (int off = 16; off; off >>= 1)
                a1[e] += __shfl_xor_sync(0xFFFFFFFFu, a1[e], off);
        }
        if (lane == 0) {
#pragma unroll
            for (int t = 0; t < 2; t++) {
                float* l = t ? a1 : a0;
                int tk = tok + t;
                ((float4*)logits_out)[tk * 2]     = make_float4(l[0], l[1], l[2], l[3]);
                ((float4*)logits_out)[tk * 2 + 1] = make_float4(l[4], l[5], l[6], l[7]);
                int i1 = 0; float l1 = l[0];
#pragma unroll
                for (int e = 1; e < NEXP; e++) if (l[e] > l1) { l1 = l[e]; i1 = e; }
                int i2 = -1; float l2 = -3.4e38f;
#pragma unroll
                for (int e = 0; e < NEXP; e++)
                    if (e != i1 && l[e] > l2) { l2 = l[e]; i2 = e; }
                float ex = expf(l2 - l1);
                float w1 = 1.0f / (1.0f + ex);
                float w2 = ex / (1.0f + ex);
                int p1 = atomicAdd(&g_cursor[i1], 1);
                int s1 = i1 * T_TOK + p1;
                g_slot_token[s1] = tk;  g_slot_w[s1] = w1;
                g_tok_slot[tk * 2] = s1;
                int p2 = atomicAdd(&g_cursor[i2], 1);
                int s2 = i2 * T_TOK + p2;
                g_slot_token[s2] = tk;  g_slot_w[s2] = w2;
                g_tok_slot[tk * 2 + 1] = s2;
            }
        }
    } else if (blockIdx.x < RBLK + X2BLK) {
        // ---- x split-convert: one block per token, 32 B per thread ----
        int tok = blockIdx.x - RBLK;
        int tid = threadIdx.x;
        const float4* xr = (const float4*)x + (size_t)tok * 512;
        float4 v0 = xr[tid * 2];
        float4 v1 = xr[tid * 2 + 1];
        uint32_t h0, u0, h1, u1, h2, u2, h3, u3;
        split2(v0.x, v0.y, h0, u0, 1.0f);
        split2(v0.z, v0.w, h1, u1, 1.0f);
        split2(v1.x, v1.y, h2, u2, 1.0f);
        split2(v1.z, v1.w, h3, u3, 1.0f);
        uint4* xc4 = (uint4*)g_xc + (size_t)tok * 512;   // 512 uint4 per row
        xc4[tid]       = make_uint4(h0, h1, h2, h3);     // xh half
        xc4[256 + tid] = make_uint4(u0, u1, u2, u3);     // u half
    } else {
        // ---- w split-convert: 32 B per thread ----
        size_t p = (size_t)(blockIdx.x - RBLK - X2BLK) * 256 + threadIdx.x;
        int row = (int)(p >> 8);                         // e*HDIM + n
        int cp  = (int)(p & 255);                        // pair index in row
        const float4* wr = (const float4*)ew + (size_t)row * 512;
        float4 v0 = wr[cp * 2];
        float4 v1 = wr[cp * 2 + 1];
        uint32_t h0, u0, h1, u1, h2, u2, h3, u3;
        // post=32 scales the correction term exactly (power of 2 in fp16)
        split2(v0.x * 64.f, v0.y * 64.f, h0, u0, 32.0f);
        split2(v0.z * 64.f, v0.w * 64.f, h1, u1, 32.0f);
        split2(v1.x * 64.f, v1.y * 64.f, h2, u2, 32.0f);
        split2(v1.z * 64.f, v1.w * 64.f, h3, u3, 32.0f);
        uint4* wc4 = (uint4*)g_wc + (size_t)row * 512;
        wc4[cp]       = make_uint4(h0, h1, h2, h3);      // wh half
        wc4[256 + cp] = make_uint4(u0, u1, u2, u3);      // 32v half
    }
}

// ============================================================================
// K2: grouped GEMM — 128x128xK4096 merged Ootomo, single fp32 acc set,
// 4 warps (2x2 grid, 64x64 warp tile), 2 CTAs/SM, 4-stage cp.async, SW64.
// Self-scheduling: each CTA derives (expert, mbase) from g_cursor with an
// 8-step prefix walk (no tile map, no scan kernel).
// Single __syncthreads per k-step; stage (kt+3)&3 was consumed in kt-1.
// Mid-loop: acc *= 31/32 (fp32-exact) between the xh*wh and u*32v halves.
// Epilogue: weighted rows -> ybuf (padding rows never read by combine).
// ============================================================================
#define MAT_B     8192                        // 128 rows x 64B
#define STAGE_B   (2 * MAT_B)                 // 16384 (A, B)
#define NSTAGE    4
#define SMEM_DYN  (1024 + NSTAGE * STAGE_B)   // 66560 B -> 2 CTAs/SM

__global__ void __launch_bounds__(128, 2)
moe_gemm_kernel() {
    // per-CTA tile schedule from cursors (8 L2-hot ints)
    int tile = blockIdx.y;
    int e = -1, mbase = 0, nt = 0;
#pragma unroll
    for (int ee = 0; ee < NEXP; ee++) {
        int tiles = (g_cursor[ee] + 127) >> 7;
        if (e < 0 && tile < nt + tiles) {
            e = ee;
            mbase = ee * T_TOK + (tile - nt) * 128;
        }
        nt += tiles;
    }
    if (e < 0) return;
    int n0 = blockIdx.x * 128;

    extern __shared__ char dsm[];
    float* s_fr    = (float*)dsm;             // 128: slotw/64 per row
    int*   s_token = (int*)(dsm + 512);       // 128: token per row
    uint32_t st0 = smem_to_u32(dsm) + 1024;

    int tid = threadIdx.x, lane = tid & 31, wid = tid >> 5;
    int wm = wid >> 1, wn = wid & 1;          // 2x2 grid, warp 64(M)x64(N)

    if (tid < 128) {
        s_fr[tid]    = g_slot_w[mbase + tid] * (1.0f / 64.0f);
        s_token[tid] = g_slot_token[mbase + tid];
    }
    __syncthreads();

    const __half* Bg = g_wc + ((size_t)e * HDIM + n0) * KCAT;

    // precompute per-thread fill pointers (8 chunks: 4 A via token gather, 4 B)
    const __half* gsrc[8];
    uint32_t sdst[8];
#pragma unroll
    for (int i = 0; i < 8; i++) {
        int cid = tid + i * 128;
        int mat = cid >> 9;                   // 0=A, 1=B
        int win = cid & 511;
        int rr  = win >> 2;
        int cc  = win & 3;
        if (mat == 0) {
            int tok = s_token[rr];
            gsrc[i] = g_xc + (size_t)tok * KCAT + cc * 8;
        } else {
            gsrc[i] = Bg + (size_t)rr * KCAT + cc * 8;
        }
        sdst[i] = st0 + mat * MAT_B + SW64((uint32_t)(rr * 64 + cc * 16));
    }

    auto fill = [&](int stage, int kt) {
        uint32_t so = (uint32_t)(stage * STAGE_B);
        int k0 = kt * 32;
#pragma unroll
        for (int i = 0; i < 8; i++)
            CP_ASYNC16(sdst[i] + so, gsrc[i] + k0);
    };

    fill(0, 0); CP_COMMIT();
    fill(1, 1); CP_COMMIT();
    fill(2, 2); CP_COMMIT();

    float acc[4][8][4];
#pragma unroll
    for (int a = 0; a < 4; a++)
#pragma unroll
        for (int b = 0; b < 8; b++)
#pragma unroll
            for (int c = 0; c < 4; c++) acc[a][b][c] = 0.f;

    for (int kt = 0; kt < KSTEPS; kt++) {
        // between halves: acc = T1 -> scale by 31/32 (fp32-exact cancellation)
        if (kt == KSTEPS / 2) {
#pragma unroll
            for (int a = 0; a < 4; a++)
#pragma unroll
                for (int b = 0; b < 8; b++)
#pragma unroll
                    for (int c = 0; c < 4; c++) acc[a][b][c] *= 0.96875f;
        }
        CP_WAIT2();
        __syncthreads();                      // single sync per k-step

        int nxt = kt + 3;                     // stage (kt+3)&3 was read in kt-1
        if (nxt < KSTEPS) fill(nxt & 3, nxt);
        CP_COMMIT();

        uint32_t sbase = st0 + (kt & 3) * STAGE_B;
        uint32_t sA = sbase, sB = sbase + MAT_B;
#pragma unroll
        for (int k16 = 0; k16 < 2; k16++) {
            uint32_t af[4][4];
#pragma unroll
            for (int mi = 0; mi < 4; mi++) {
                uint32_t ad = SW64((uint32_t)(
                    (wm * 64 + mi * 16 + (lane & 15)) * 64
                    + k16 * 32 + (lane >> 4) * 16));
                ldsm_x4(af[mi], sA + ad);
            }
            uint32_t bf[4][4];
#pragma unroll
            for (int jj = 0; jj < 4; jj++) {
                uint32_t bd = SW64((uint32_t)(
                    (wn * 64 + jj * 16 + ((lane >> 4) << 3) + (lane & 7)) * 64
                    + k16 * 32 + (((lane >> 3) & 1) << 4)));
                ldsm_x4(bf[jj], sB + bd);
            }
            // 32 HMMAs per k16, acc reuse distance 32
#pragma unroll
            for (int mi = 0; mi < 4; mi++)
#pragma unroll
                for (int jj = 0; jj < 4; jj++)
#pragma unroll
                    for (int s = 0; s < 2; s++)
                        mma16816(acc[mi][jj * 2 + s], af[mi], &bf[jj][s * 2]);
        }
    }

    // epilogue: y = acc * slotw/64 -> ybuf
#pragma unroll
    for (int mi = 0; mi < 4; mi++) {
        int r0 = wm * 64 + mi * 16 + (lane >> 2);
        float f0 = s_fr[r0], f1 = s_fr[r0 + 8];
        size_t o0 = (size_t)(mbase + r0) * HDIM + n0;
#pragma unroll
        for (int n8 = 0; n8 < 8; n8++) {
            int c = wn * 64 + n8 * 8 + (lane & 3) * 2;
            *(float2*)(g_ybuf + o0 + c) =
                make_float2(acc[mi][n8][0] * f0, acc[mi][n8][1] * f0);
            *(float2*)(g_ybuf + o0 + (size_t)8 * HDIM + c) =
                make_float2(acc[mi][n8][2] * f1, acc[mi][n8][3] * f1);
        }
    }
}

// ============================================================================
// K3: combine — out[t] = ybuf[slot0(t)] + ybuf[slot1(t)]; block 0 also
// resets the cursors for the next launch (graph replay invariant; runs
// after the GEMM's g_cursor reads).
// ============================================================================
__global__ void moe_combine_kernel(float* __restrict__ out) {
    if (blockIdx.x == 0 && threadIdx.x < NEXP) g_cursor[threadIdx.x] = 0;
    int i = blockIdx.x * blockDim.x + threadIdx.x;
    int t  = i >> 9;
    int h4 = i & 511;
    int s0 = g_tok_slot[2 * t + 0];
    int s1 = g_tok_slot[2 * t + 1];
    float4 a = *(const float4*)(g_ybuf + (size_t)s0 * HDIM + h4 * 4);
    float4 b = *(const float4*)(g_ybuf + (size_t)s1 * HDIM + h4 * 4);
    float4 o;
    o.x = a.x + b.x; o.y = a.y + b.y; o.z = a.z + b.z; o.w = a.w + b.w;
    ((float4*)out)[i] = o;
}

// ============================================================================
// Launch — 3 kernels
// ============================================================================
extern "C" void kernel_launch(void* const* d_in, const int* in_sizes, int n_in,
                              void* d_out, int out_size) {
    const float* x  = (const float*)d_in[0];   // hidden_states [T, H]
    const float* gw = (const float*)d_in[1];   // gate_w [E, H]
    const float* ew = (const float*)d_in[2];   // expert_w [E, H, H]
    float* out    = (float*)d_out;             // [T, H]
    float* logits = out + (size_t)T_TOK * HDIM;

    cudaFuncSetAttribute(moe_gemm_kernel,
                         cudaFuncAttributeMaxDynamicSharedMemorySize, SMEM_DYN);

    moe_prep_kernel<<<RBLK + X2BLK + W2BLK, 256>>>(x, gw, ew, logits);
    moe_gemm_kernel<<<dim3(16, MAX_TILES), 128, SMEM_DYN>>>();
    moe_combine_kernel<<<(T_TOK * (HDIM / 4)) / 256, 256>>>(out);
}

// round 17
// speedup vs baseline: 1.6902x; 1.0123x over previous
#include <cuda_runtime.h>
#include <cuda_fp16.h>
#include <cstdint>

// ============================================================================
// Problem constants
// ============================================================================
#define T_TOK   8192          // B*S tokens
#define HDIM    2048
#define NEXP    8
#define MAX_TILES 136         // sum ceil(count_e/128) <= 2T/128 + E
#define KCAT    4096          // merged K: [xh | u] / [wh | 32v]
#define KSTEPS  128           // KCAT / 32 per k-step
#define NSLOTF  (NEXP * T_TOK)   // fixed-capacity slot space (65536)

// ============================================================================
// PTX helpers — family-portable only (mma.sync / ldmatrix / cp.async)
// ============================================================================
__device__ __forceinline__ uint32_t smem_to_u32(const void* p) {
    uint32_t a;
    asm("{ .reg .u64 t; cvta.to.shared.u64 t, %1; cvt.u32.u64 %0, t; }"
        : "=r"(a) : "l"(p));
    return a;
}

#define CP_ASYNC16(smem, gmem) \
    asm volatile("cp.async.cg.shared.global [%0], [%1], 16;" \
        :: "r"(smem), "l"(gmem))
#define CP_COMMIT() asm volatile("cp.async.commit_group;" ::: "memory")
#define CP_WAIT2()  asm volatile("cp.async.wait_group 2;" ::: "memory")

__device__ __forceinline__ void ldsm_x4(uint32_t* r, uint32_t addr) {
    asm volatile("ldmatrix.sync.aligned.m8n8.x4.shared.b16 {%0,%1,%2,%3}, [%4];"
        : "=r"(r[0]), "=r"(r[1]), "=r"(r[2]), "=r"(r[3]) : "r"(addr));
}

// m16n8k16 fp16 HMMA, fp32 accumulate
__device__ __forceinline__ void mma16816(float* d, const uint32_t* a,
                                         const uint32_t* b) {
    asm volatile(
        "mma.sync.aligned.m16n8k16.row.col.f32.f16.f16.f32 "
        "{%0,%1,%2,%3}, {%4,%5,%6,%7}, {%8,%9}, {%0,%1,%2,%3};"
        : "+f"(d[0]), "+f"(d[1]), "+f"(d[2]), "+f"(d[3])
        : "r"(a[0]), "r"(a[1]), "r"(a[2]), "r"(a[3]), "r"(b[0]), "r"(b[1]));
}

// SW64 swizzle: XOR byte-offset bits[5:4] with bits[8:7] (row bits for 64B rows)
#define SW64(off) ((off) ^ (((off) >> 3) & 0x30))

// ============================================================================
// Device scratch — fixed-capacity slot layout: slot = e*T_TOK + pos.
// g_cursor must be 0 on entry of every launch: zero-init covers call 1;
// the combine kernel clears it at the end of each launch (graph-replay safe,
// deterministic — routing depends only on inputs).
// ============================================================================
__device__ int    g_cursor[NEXP];
__device__ int    g_slot_token[NSLOTF];    // zero-init; stale values stay in
__device__ float  g_slot_w[NSLOTF];        //   [0,T) so always a valid index
__device__ int    g_tok_slot[T_TOK * 2];

__device__ __half g_xc[(size_t)T_TOK * KCAT];              // 67 MB [xh | u], per TOKEN
__device__ __half g_wc[(size_t)NEXP * HDIM * KCAT];        // 134 MB [wh | 32v]
__device__ float  g_ybuf[(size_t)NSLOTF * HDIM];           // 536 MB, sparse-written

// ============================================================================
// K1: fused prep — batch-2 router + 64B/thread split-converts (MLP 4).
// Router: 512 blocks x 8 warps x 2 tokens (bit-identical logits).
// Converts: each thread loads 4 consecutive float4 (64 B in flight) and
// writes 4 uint4 stores — deeper MLP to cross the BW*latency knee that
// capped R16 at 58.8% DRAM.
//
// Ootomo split:
//   A row (4096): [ xh = fp16(x) | u = fp16(xh/32 + (x-xh)) ]
//   B row (4096): [ wh = fp16(64w) | 32*fp16(wh/32 + (64w-wh)) ]  (32x exact)
// ============================================================================
#define RBLK  (T_TOK / 16)                        // 512 router blocks
#define X4BLK (T_TOK / 2)                         // 4096: 2 tokens per block
#define W4BLK (NEXP * HDIM / 2)                   // 8192 w-convert blocks

__device__ __forceinline__ void split2(float a, float b, uint32_t& h,
                                       uint32_t& u, float post) {
    __half2 hh = __floats2half2_rn(a, b);
    float2 hf = __half22float2(hh);
    __half2 uu = __floats2half2_rn((hf.x * 0.03125f + (a - hf.x)) * post,
                                   (hf.y * 0.03125f + (b - hf.y)) * post);
    h = *(uint32_t*)&hh;
    u = *(uint32_t*)&uu;
}

// split 4 float4 (scaled by pre) into 2 uint4 hi + 2 uint4 lo (post on lo)
__device__ __forceinline__ void split_quad(const float4* src, float pre,
                                           float post, uint4* h4, uint4* u4) {
    uint32_t h[8], u[8];
#pragma unroll
    for (int k = 0; k < 4; k++) {
        float4 v = src[k];
        split2(v.x * pre, v.y * pre, h[k * 2], u[k * 2], post);
        split2(v.z * pre, v.w * pre, h[k * 2 + 1], u[k * 2 + 1], post);
    }
    h4[0] = make_uint4(h[0], h[1], h[2], h[3]);
    h4[1] = make_uint4(h[4], h[5], h[6], h[7]);
    u4[0] = make_uint4(u[0], u[1], u[2], u[3]);
    u4[1] = make_uint4(u[4], u[5], u[6], u[7]);
}

__global__ void moe_prep_kernel(const float* __restrict__ x,
                                const float* __restrict__ gw,
                                const float* __restrict__ ew,
                                float* __restrict__ logits_out) {
    if (blockIdx.x < RBLK) {
        // ---- router: warp handles 2 tokens; gw loads amortized x2 ----
        int w = threadIdx.x >> 5, lane = threadIdx.x & 31;
        int tok = blockIdx.x * 16 + w * 2;          // tokens tok, tok+1
        const float4* x0 = (const float4*)(x + (size_t)tok * HDIM);
        const float4* x1 = (const float4*)(x + (size_t)(tok + 1) * HDIM);
        float a0[NEXP], a1[NEXP];
#pragma unroll
        for (int e = 0; e < NEXP; e++) { a0[e] = 0.f; a1[e] = 0.f; }
        for (int i = 0; i < 16; i++) {
            float4 v0 = x0[i * 32 + lane];
            float4 v1 = x1[i * 32 + lane];
#pragma unroll
            for (int e = 0; e < NEXP; e++) {
                float4 gv = ((const float4*)(gw + e * HDIM))[i * 32 + lane];
                a0[e] += v0.x * gv.x + v0.y * gv.y + v0.z * gv.z + v0.w * gv.w;
                a1[e] += v1.x * gv.x + v1.y * gv.y + v1.z * gv.z + v1.w * gv.w;
            }
        }
#pragma unroll
        for (int e = 0; e < NEXP; e++) {
#pragma unroll
            for (int off = 16; off; off >>= 1)
                a0[e] += __shfl_xor_sync(0xFFFFFFFFu, a0[e], off);
#pragma unroll
            for (int off = 16; off; off >>= 1)
                a1[e] += __shfl_xor_sync(0xFFFFFFFFu, a1[e], off);
        }
        if (lane == 0) {
#pragma unroll
            for (int t = 0; t < 2; t++) {
                float* l = t ? a1 : a0;
                int tk = tok + t;
                ((float4*)logits_out)[tk * 2]     = make_float4(l[0], l[1], l[2], l[3]);
                ((float4*)logits_out)[tk * 2 + 1] = make_float4(l[4], l[5], l[6], l[7]);
                int i1 = 0; float l1 = l[0];
#pragma unroll
                for (int e = 1; e < NEXP; e++) if (l[e] > l1) { l1 = l[e]; i1 = e; }
                int i2 = -1; float l2 = -3.4e38f;
#pragma unroll
                for (int e = 0; e < NEXP; e++)
                    if (e != i1 && l[e] > l2) { l2 = l[e]; i2 = e; }
                float ex = expf(l2 - l1);
                float w1 = 1.0f / (1.0f + ex);
                float w2 = ex / (1.0f + ex);
                int p1 = atomicAdd(&g_cursor[i1], 1);
                int s1 = i1 * T_TOK + p1;
                g_slot_token[s1] = tk;  g_slot_w[s1] = w1;
                g_tok_slot[tk * 2] = s1;
                int p2 = atomicAdd(&g_cursor[i2], 1);
                int s2 = i2 * T_TOK + p2;
                g_slot_token[s2] = tk;  g_slot_w[s2] = w2;
                g_tok_slot[tk * 2 + 1] = s2;
            }
        }
    } else if (blockIdx.x < RBLK + X4BLK) {
        // ---- x split-convert: 2 tokens/block, 64 B per thread ----
        int blk = blockIdx.x - RBLK;
        int tok = blk * 2 + (threadIdx.x >> 7);
        int q   = threadIdx.x & 127;                 // quad of 4 float4
        const float4* xr = (const float4*)x + (size_t)tok * 512 + q * 4;
        float4 v[4] = {xr[0], xr[1], xr[2], xr[3]};
        uint4 h4[2], u4[2];
        split_quad(v, 1.0f, 1.0f, h4, u4);
        uint4* xc4 = (uint4*)g_xc + (size_t)tok * 512;  // 512 uint4 per row
        xc4[q * 2]           = h4[0];                    // xh half
        xc4[q * 2 + 1]       = h4[1];
        xc4[256 + q * 2]     = u4[0];                    // u half
        xc4[256 + q * 2 + 1] = u4[1];
    } else {
        // ---- w split-convert: 64 B per thread ----
        size_t p = (size_t)(blockIdx.x - RBLK - X4BLK) * 256 + threadIdx.x;
        int row = (int)(p >> 7);                         // e*HDIM + n
        int q   = (int)(p & 127);
        const float4* wr = (const float4*)ew + (size_t)row * 512 + q * 4;
        float4 v[4] = {wr[0], wr[1], wr[2], wr[3]};
        uint4 h4[2], u4[2];
        // pre=64 value scale; post=32 on correction (both exact powers of 2)
        split_quad(v, 64.0f, 32.0f, h4, u4);
        uint4* wc4 = (uint4*)g_wc + (size_t)row * 512;
        wc4[q * 2]           = h4[0];                    // wh half
        wc4[q * 2 + 1]       = h4[1];
        wc4[256 + q * 2]     = u4[0];                    // 32v half
        wc4[256 + q * 2 + 1] = u4[1];
    }
}

// ============================================================================
// K2: grouped GEMM — 128x128xK4096 merged Ootomo, single fp32 acc set,
// 4 warps (2x2 grid, 64x64 warp tile), 2 CTAs/SM, 4-stage cp.async, SW64.
// Self-scheduling: each CTA derives (expert, mbase) from g_cursor with an
// 8-step prefix walk (no tile map, no scan kernel).
// Single __syncthreads per k-step; stage (kt+3)&3 was consumed in kt-1.
// Mid-loop: acc *= 31/32 (fp32-exact) between the xh*wh and u*32v halves.
// Epilogue: weighted rows -> ybuf (padding rows never read by combine).
// At the measured HMMA issue floor (7.13e7 warp-HMMAs @ rt=8) — do not touch.
// ============================================================================
#define MAT_B     8192                        // 128 rows x 64B
#define STAGE_B   (2 * MAT_B)                 // 16384 (A, B)
#define NSTAGE    4
#define SMEM_DYN  (1024 + NSTAGE * STAGE_B)   // 66560 B -> 2 CTAs/SM

__global__ void __launch_bounds__(128, 2)
moe_gemm_kernel() {
    // per-CTA tile schedule from cursors (8 L2-hot ints)
    int tile = blockIdx.y;
    int e = -1, mbase = 0, nt = 0;
#pragma unroll
    for (int ee = 0; ee < NEXP; ee++) {
        int tiles = (g_cursor[ee] + 127) >> 7;
        if (e < 0 && tile < nt + tiles) {
            e = ee;
            mbase = ee * T_TOK + (tile - nt) * 128;
        }
        nt += tiles;
    }
    if (e < 0) return;
    int n0 = blockIdx.x * 128;

    extern __shared__ char dsm[];
    float* s_fr    = (float*)dsm;             // 128: slotw/64 per row
    int*   s_token = (int*)(dsm + 512);       // 128: token per row
    uint32_t st0 = smem_to_u32(dsm) + 1024;

    int tid = threadIdx.x, lane = tid & 31, wid = tid >> 5;
    int wm = wid >> 1, wn = wid & 1;          // 2x2 grid, warp 64(M)x64(N)

    if (tid < 128) {
        s_fr[tid]    = g_slot_w[mbase + tid] * (1.0f / 64.0f);
        s_token[tid] = g_slot_token[mbase + tid];
    }
    __syncthreads();

    const __half* Bg = g_wc + ((size_t)e * HDIM + n0) * KCAT;

    // precompute per-thread fill pointers (8 chunks: 4 A via token gather, 4 B)
    const __half* gsrc[8];
    uint32_t sdst[8];
#pragma unroll
    for (int i = 0; i < 8; i++) {
        int cid = tid + i * 128;
        int mat = cid >> 9;                   // 0=A, 1=B
        int win = cid & 511;
        int rr  = win >> 2;
        int cc  = win & 3;
        if (mat == 0) {
            int tok = s_token[rr];
            gsrc[i] = g_xc + (size_t)tok * KCAT + cc * 8;
        } else {
            gsrc[i] = Bg + (size_t)rr * KCAT + cc * 8;
        }
        sdst[i] = st0 + mat * MAT_B + SW64((uint32_t)(rr * 64 + cc * 16));
    }

    auto fill = [&](int stage, int kt) {
        uint32_t so = (uint32_t)(stage * STAGE_B);
        int k0 = kt * 32;
#pragma unroll
        for (int i = 0; i < 8; i++)
            CP_ASYNC16(sdst[i] + so, gsrc[i] + k0);
    };

    fill(0, 0); CP_COMMIT();
    fill(1, 1); CP_COMMIT();
    fill(2, 2); CP_COMMIT();

    float acc[4][8][4];
#pragma unroll
    for (int a = 0; a < 4; a++)
#pragma unroll
        for (int b = 0; b < 8; b++)
#pragma unroll
            for (int c = 0; c < 4; c++) acc[a][b][c] = 0.f;

    for (int kt = 0; kt < KSTEPS; kt++) {
        // between halves: acc = T1 -> scale by 31/32 (fp32-exact cancellation)
        if (kt == KSTEPS / 2) {
#pragma unroll
            for (int a = 0; a < 4; a++)
#pragma unroll
                for (int b = 0; b < 8; b++)
#pragma unroll
                    for (int c = 0; c < 4; c++) acc[a][b][c] *= 0.96875f;
        }
        CP_WAIT2();
        __syncthreads();                      // single sync per k-step

        int nxt = kt + 3;                     // stage (kt+3)&3 was read in kt-1
        if (nxt < KSTEPS) fill(nxt & 3, nxt);
        CP_COMMIT();

        uint32_t sbase = st0 + (kt & 3) * STAGE_B;
        uint32_t sA = sbase, sB = sbase + MAT_B;
#pragma unroll
        for (int k16 = 0; k16 < 2; k16++) {
            uint32_t af[4][4];
#pragma unroll
            for (int mi = 0; mi < 4; mi++) {
                uint32_t ad = SW64((uint32_t)(
                    (wm * 64 + mi * 16 + (lane & 15)) * 64
                    + k16 * 32 + (lane >> 4) * 16));
                ldsm_x4(af[mi], sA + ad);
            }
            uint32_t bf[4][4];
#pragma unroll
            for (int jj = 0; jj < 4; jj++) {
                uint32_t bd = SW64((uint32_t)(
                    (wn * 64 + jj * 16 + ((lane >> 4) << 3) + (lane & 7)) * 64
                    + k16 * 32 + (((lane >> 3) & 1) << 4)));
                ldsm_x4(bf[jj], sB + bd);
            }
            // 32 HMMAs per k16, acc reuse distance 32
#pragma unroll
            for (int mi = 0; mi < 4; mi++)
#pragma unroll
                for (int jj = 0; jj < 4; jj++)
#pragma unroll
                    for (int s = 0; s < 2; s++)
                        mma16816(acc[mi][jj * 2 + s], af[mi], &bf[jj][s * 2]);
        }
    }

    // epilogue: y = acc * slotw/64 -> ybuf
#pragma unroll
    for (int mi = 0; mi < 4; mi++) {
        int r0 = wm * 64 + mi * 16 + (lane >> 2);
        float f0 = s_fr[r0], f1 = s_fr[r0 + 8];
        size_t o0 = (size_t)(mbase + r0) * HDIM + n0;
#pragma unroll
        for (int n8 = 0; n8 < 8; n8++) {
            int c = wn * 64 + n8 * 8 + (lane & 3) * 2;
            *(float2*)(g_ybuf + o0 + c) =
                make_float2(acc[mi][n8][0] * f0, acc[mi][n8][1] * f0);
            *(float2*)(g_ybuf + o0 + (size_t)8 * HDIM + c) =
                make_float2(acc[mi][n8][2] * f1, acc[mi][n8][3] * f1);
        }
    }
}

// ============================================================================
// K3: combine — out[t] = ybuf[slot0(t)] + ybuf[slot1(t)], 2 float4s per
// thread (MLP 4); block 0 also resets the cursors for the next launch
// (graph replay invariant; runs after the GEMM's g_cursor reads).
// ============================================================================
__global__ void moe_combine_kernel(float* __restrict__ out) {
    if (blockIdx.x == 0 && threadIdx.x < NEXP) g_cursor[threadIdx.x] = 0;
    int j = blockIdx.x * blockDim.x + threadIdx.x;   // pair index, T*256 total
    int t  = j >> 8;
    int h8 = (j & 255) * 2;                           // float4 index in row
    int s0 = g_tok_slot[2 * t + 0];
    int s1 = g_tok_slot[2 * t + 1];
    const float4* r0 = (const float4*)(g_ybuf + (size_t)s0 * HDIM) + h8;
    const float4* r1 = (const float4*)(g_ybuf + (size_t)s1 * HDIM) + h8;
    float4 a0 = r0[0], a1 = r0[1];
    float4 b0 = r1[0], b1 = r1[1];
    float4 o0, o1;
    o0.x = a0.x + b0.x; o0.y = a0.y + b0.y; o0.z = a0.z + b0.z; o0.w = a0.w + b0.w;
    o1.x = a1.x + b1.x; o1.y = a1.y + b1.y; o1.z = a1.z + b1.z; o1.w = a1.w + b1.w;
    float4* op = (float4*)out + (size_t)t * 512 + h8;
    op[0] = o0;
    op[1] = o1;
}

// ============================================================================
// Launch — 3 kernels
// ============================================================================
extern "C" void kernel_launch(void* const* d_in, const int* in_sizes, int n_in,
                              void* d_out, int out_size) {
    const float* x  = (const float*)d_in[0];   // hidden_states [T, H]
    const float* gw = (const float*)d_in[1];   // gate_w [E, H]
    const float* ew = (const float*)d_in[2];   // expert_w [E, H, H]
    float* out    = (float*)d_out;             // [T, H]
    float* logits = out + (size_t)T_TOK * HDIM;

    cudaFuncSetAttribute(moe_gemm_kernel,
                         cudaFuncAttributeMaxDynamicSharedMemorySize, SMEM_DYN);

    moe_prep_kernel<<<RBLK + X4BLK + W4BLK, 256>>>(x, gw, ew, logits);
    moe_gemm_kernel<<<dim3(16, MAX_TILES), 128, SMEM_DYN>>>();
    moe_combine_kernel<<<(T_TOK * 256) / 256, 256>>>(out);
}